// round 13
// baseline (speedup 1.0000x reference)
#include <cuda_runtime.h>
#include <cuda_bf16.h>
#include <cub/cub.cuh>

// Problem shape (TokenSelector_83708912599683)
#define BB 32
#define SS 65536
#define DD 32
#define HH 16

// Scratch: __device__ globals (runtime allocation is forbidden)
__device__ float        g_keys[BB * SS];
__device__ unsigned int g_vals[BB * SS];
__device__ float        g_keys_out[BB * SS];
__device__ unsigned int g_vals_out[BB * SS];
__device__ int          g_offsets[BB + 1];
__device__ unsigned char g_temp[64 * 1024 * 1024];

__global__ void init_offsets_kernel() {
    int i = threadIdx.x;
    if (i <= BB) g_offsets[i] = i * SS;
}

// Cephes/Pommier expf, all ops single-rounded & UNFUSED (R10, best so far),
// EXCEPT the final polynomial combine y = y*z + x which is FUSED (fmaf).
// Rationale: R10 residual (~1.6% bit disagreement) matches exactly the
// rounding-error footprint of that one op being fused in the reference.
__device__ __forceinline__ float ref_expf(float x0) {
    float x = fminf(x0, 88.8f);
    x = fmaxf(x, -88.8f);
    float fx = floorf(__fadd_rn(__fmul_rn(x, 1.44269504088896341f), 0.5f));
    float tmp = __fmul_rn(fx, 0.693359375f);
    float zc  = __fmul_rn(fx, -2.12194440e-4f);
    x = __fsub_rn(x, tmp);
    x = __fsub_rn(x, zc);
    float z = __fmul_rn(x, x);
    float y = 1.9875691500E-4f;
    y = __fadd_rn(__fmul_rn(y, x), 1.3981999507E-3f);
    y = __fadd_rn(__fmul_rn(y, x), 8.3334519073E-3f);
    y = __fadd_rn(__fmul_rn(y, x), 4.1665795894E-2f);
    y = __fadd_rn(__fmul_rn(y, x), 1.6666665459E-1f);
    y = __fadd_rn(__fmul_rn(y, x), 5.0000001201E-1f);
    y = fmaf(y, z, x);                   // <-- the single changed op (fused)
    y = __fadd_rn(y, 1.0f);
    int n = (int)fx;
    float p2n = __int_as_float((n + 127) << 23);
    return __fmul_rn(y, p2n);
}

// One thread per (b, s): tiny MLP scorer.
// einsum1 (D->H): sequential-d fused-fma chain (Eigen gebp) — confirmed.
// einsum2 (H->1): sequential-j fused-fma chain (Eigen gemv) — confirmed
//   (R11's unfused variant regressed 6.8e-3 -> 3.1e-2).
// sigmoid: 1/(1 + ref_expf(-z)), add/div single-rounded.
__global__ void score_kernel(const float* __restrict__ emb,
                             const float* __restrict__ W1,
                             const float* __restrict__ b1,
                             const float* __restrict__ W2,
                             const float* __restrict__ b2,
                             float* __restrict__ scores_out) {
    __shared__ float sW1[DD * HH];
    __shared__ float sb1[HH];
    __shared__ float sW2[HH];
    __shared__ float sb2;

    int t = threadIdx.x;
    for (int idx = t; idx < DD * HH; idx += blockDim.x) sW1[idx] = W1[idx];
    if (t < HH) { sb1[t] = b1[t]; sW2[t] = W2[t]; }
    if (t == 0) sb2 = b2[0];
    __syncthreads();

    long long i = (long long)blockIdx.x * blockDim.x + t;
    if (i >= (long long)BB * SS) return;

    const float4* row = (const float4*)(emb + i * DD);
    float h[HH];
#pragma unroll
    for (int j = 0; j < HH; j++) h[j] = 0.0f;

#pragma unroll
    for (int q = 0; q < DD / 4; q++) {
        float4 x = row[q];
#pragma unroll
        for (int j = 0; j < HH; j++) {
            h[j] = fmaf(x.x, sW1[(4 * q + 0) * HH + j], h[j]);
            h[j] = fmaf(x.y, sW1[(4 * q + 1) * HH + j], h[j]);
            h[j] = fmaf(x.z, sW1[(4 * q + 2) * HH + j], h[j]);
            h[j] = fmaf(x.w, sW1[(4 * q + 3) * HH + j], h[j]);
        }
    }

    float z = 0.0f;
#pragma unroll
    for (int j = 0; j < HH; j++) {
        float a = fmaxf(__fadd_rn(h[j], sb1[j]), 0.0f);
        z = fmaf(a, sW2[j], z);
    }
    z = __fadd_rn(z, sb2);

    float e  = ref_expf(-z);
    float sc = __fdiv_rn(1.0f, __fadd_rn(1.0f, e));

    scores_out[i] = sc;
    g_keys[i] = sc;
    g_vals[i] = (unsigned int)(i & (SS - 1));  // local index within batch
}

// Gather selected rows + write indices (as float) from the sorted result.
__global__ void gather_kernel(const float* __restrict__ emb,
                              float* __restrict__ out, int k) {
    long long tid = (long long)blockIdx.x * blockDim.x + threadIdx.x;
    long long total = (long long)BB * k * (DD / 4);
    if (tid >= total) return;

    int q = (int)(tid % (DD / 4));
    long long bi = tid / (DD / 4);           // b * k + i
    int i = (int)(bi % k);
    int b = (int)(bi / k);

    unsigned int idx = g_vals_out[(long long)b * SS + i];

    const float4* src = (const float4*)(emb + ((long long)b * SS + idx) * DD);
    float4* dst = (float4*)(out + bi * DD);
    dst[q] = src[q];

    if (q == 0) {
        out[(long long)BB * k * DD + bi] = (float)idx;
    }
}

extern "C" void kernel_launch(void* const* d_in, const int* in_sizes, int n_in,
                              void* d_out, int out_size) {
    const float* emb = (const float*)d_in[0];
    const float* W1  = (const float*)d_in[1];
    const float* b1  = (const float*)d_in[2];
    const float* W2  = (const float*)d_in[3];
    const float* b2  = (const float*)d_in[4];
    float* out = (float*)d_out;

    // out = [sel: B*k*D][idx: B*k][scores: B*S]  (all f32)
    int k = (out_size - BB * SS) / (BB * (DD + 1));
    if (k < 1) k = 1;
    if (k > SS) k = SS;

    float* scores_out = out + (long long)BB * k * DD + (long long)BB * k;

    init_offsets_kernel<<<1, 64>>>();

    {
        long long n = (long long)BB * SS;
        int threads = 256;
        int blocks = (int)((n + threads - 1) / threads);
        score_kernel<<<blocks, threads>>>(emb, W1, b1, W2, b2, scores_out);
    }

    // Resolve scratch symbol addresses (host-side, capture-safe, no allocs)
    float *keys_in, *keys_out;
    unsigned int *vals_in, *vals_out;
    int* offs;
    void* tempbuf;
    cudaGetSymbolAddress((void**)&keys_in,  g_keys);
    cudaGetSymbolAddress((void**)&keys_out, g_keys_out);
    cudaGetSymbolAddress((void**)&vals_in,  g_vals);
    cudaGetSymbolAddress((void**)&vals_out, g_vals_out);
    cudaGetSymbolAddress((void**)&offs,     g_offsets);
    cudaGetSymbolAddress(&tempbuf,          g_temp);

    size_t temp_bytes = 0;
    cub::DeviceSegmentedRadixSort::SortPairsDescending(
        nullptr, temp_bytes,
        keys_in, keys_out, vals_in, vals_out,
        BB * SS, BB, offs, offs + 1, 0, 32, (cudaStream_t)0);

    if (temp_bytes > sizeof(g_temp)) temp_bytes = sizeof(g_temp);  // guarded

    cub::DeviceSegmentedRadixSort::SortPairsDescending(
        tempbuf, temp_bytes,
        keys_in, keys_out, vals_in, vals_out,
        BB * SS, BB, offs, offs + 1, 0, 32, (cudaStream_t)0);

    {
        long long n = (long long)BB * k * (DD / 4);
        int threads = 256;
        int blocks = (int)((n + threads - 1) / threads);
        gather_kernel<<<blocks, threads>>>(emb, out, k);
    }
}

// round 14
// speedup vs baseline: 1.9293x; 1.9293x over previous
#include <cuda_runtime.h>
#include <cuda_bf16.h>
#include <cub/cub.cuh>

// Problem shape (TokenSelector_83708912599683)
#define BB 32
#define SS 65536
#define DD 32
#define HH 16

// Scratch: __device__ globals (runtime allocation is forbidden)
__device__ unsigned long long g_keys64[BB * SS];      // (batch<<32) | score_bits
__device__ unsigned long long g_keys64_out[BB * SS];
__device__ unsigned int      g_vals[BB * SS];
__device__ unsigned int      g_vals_out[BB * SS];
__device__ unsigned char     g_temp[64 * 1024 * 1024];

// ===== FROZEN numerics (bit-matched to reference, R13 PASS) =====
// Cephes/Pommier expf, all ops single-rounded & UNFUSED, EXCEPT the final
// polynomial combine y = y*z + x which is FUSED (fmaf). DO NOT MODIFY.
__device__ __forceinline__ float ref_expf(float x0) {
    float x = fminf(x0, 88.8f);
    x = fmaxf(x, -88.8f);
    float fx = floorf(__fadd_rn(__fmul_rn(x, 1.44269504088896341f), 0.5f));
    float tmp = __fmul_rn(fx, 0.693359375f);
    float zc  = __fmul_rn(fx, -2.12194440e-4f);
    x = __fsub_rn(x, tmp);
    x = __fsub_rn(x, zc);
    float z = __fmul_rn(x, x);
    float y = 1.9875691500E-4f;
    y = __fadd_rn(__fmul_rn(y, x), 1.3981999507E-3f);
    y = __fadd_rn(__fmul_rn(y, x), 8.3334519073E-3f);
    y = __fadd_rn(__fmul_rn(y, x), 4.1665795894E-2f);
    y = __fadd_rn(__fmul_rn(y, x), 1.6666665459E-1f);
    y = __fadd_rn(__fmul_rn(y, x), 5.0000001201E-1f);
    y = fmaf(y, z, x);                   // fused (frozen)
    y = __fadd_rn(y, 1.0f);
    int n = (int)fx;
    float p2n = __int_as_float((n + 127) << 23);
    return __fmul_rn(y, p2n);
}

// One thread per (b, s): tiny MLP scorer. Arithmetic FROZEN (R13 PASS):
// einsum1: sequential-d fused-fma chain; einsum2: sequential-j fused-fma
// chain; sigmoid via ref_expf; add/div single-rounded.
__global__ void score_kernel(const float* __restrict__ emb,
                             const float* __restrict__ W1,
                             const float* __restrict__ b1,
                             const float* __restrict__ W2,
                             const float* __restrict__ b2,
                             float* __restrict__ scores_out) {
    __shared__ float sW1[DD * HH];
    __shared__ float sb1[HH];
    __shared__ float sW2[HH];
    __shared__ float sb2;

    int t = threadIdx.x;
    for (int idx = t; idx < DD * HH; idx += blockDim.x) sW1[idx] = W1[idx];
    if (t < HH) { sb1[t] = b1[t]; sW2[t] = W2[t]; }
    if (t == 0) sb2 = b2[0];
    __syncthreads();

    long long i = (long long)blockIdx.x * blockDim.x + t;
    if (i >= (long long)BB * SS) return;

    const float4* row = (const float4*)(emb + i * DD);
    float h[HH];
#pragma unroll
    for (int j = 0; j < HH; j++) h[j] = 0.0f;

#pragma unroll
    for (int q = 0; q < DD / 4; q++) {
        float4 x = row[q];
#pragma unroll
        for (int j = 0; j < HH; j++) {
            h[j] = fmaf(x.x, sW1[(4 * q + 0) * HH + j], h[j]);
            h[j] = fmaf(x.y, sW1[(4 * q + 1) * HH + j], h[j]);
            h[j] = fmaf(x.z, sW1[(4 * q + 2) * HH + j], h[j]);
            h[j] = fmaf(x.w, sW1[(4 * q + 3) * HH + j], h[j]);
        }
    }

    float z = 0.0f;
#pragma unroll
    for (int j = 0; j < HH; j++) {
        float a = fmaxf(__fadd_rn(h[j], sb1[j]), 0.0f);
        z = fmaf(a, sW2[j], z);
    }
    z = __fadd_rn(z, sb2);

    float e  = ref_expf(-z);
    float sc = __fdiv_rn(1.0f, __fadd_rn(1.0f, e));

    scores_out[i] = sc;
    // Composite key: batch in bits [32,37), score bits in [0,32).
    // Scores are positive floats -> uint order == float order.
    unsigned int b = (unsigned int)(i >> 16);          // i / SS
    g_keys64[i] = ((unsigned long long)b << 32) | (unsigned long long)__float_as_uint(sc);
    g_vals[i] = (unsigned int)(i & (SS - 1));          // local index in batch
}

// Gather selected rows + write indices (as float) from the sorted result.
// Descending sort on (batch<<32|score) => batch b's segment starts at
// (BB-1-b)*SS, scores descending within, exact ties ascending index (stable).
__global__ void gather_kernel(const float* __restrict__ emb,
                              float* __restrict__ out, int k) {
    long long tid = (long long)blockIdx.x * blockDim.x + threadIdx.x;
    long long total = (long long)BB * k * (DD / 4);
    if (tid >= total) return;

    int q = (int)(tid % (DD / 4));
    long long bi = tid / (DD / 4);           // b * k + i
    int i = (int)(bi % k);
    int b = (int)(bi / k);

    unsigned int idx = g_vals_out[(long long)(BB - 1 - b) * SS + i];

    const float4* src = (const float4*)(emb + ((long long)b * SS + idx) * DD);
    float4* dst = (float4*)(out + bi * DD);
    dst[q] = src[q];

    if (q == 0) {
        out[(long long)BB * k * DD + bi] = (float)idx;
    }
}

extern "C" void kernel_launch(void* const* d_in, const int* in_sizes, int n_in,
                              void* d_out, int out_size) {
    const float* emb = (const float*)d_in[0];
    const float* W1  = (const float*)d_in[1];
    const float* b1  = (const float*)d_in[2];
    const float* W2  = (const float*)d_in[3];
    const float* b2  = (const float*)d_in[4];
    float* out = (float*)d_out;

    // out = [sel: B*k*D][idx: B*k][scores: B*S]  (all f32)
    int k = (out_size - BB * SS) / (BB * (DD + 1));
    if (k < 1) k = 1;
    if (k > SS) k = SS;

    float* scores_out = out + (long long)BB * k * DD + (long long)BB * k;

    {
        long long n = (long long)BB * SS;
        int threads = 256;
        int blocks = (int)((n + threads - 1) / threads);
        score_kernel<<<blocks, threads>>>(emb, W1, b1, W2, b2, scores_out);
    }

    // Resolve scratch symbol addresses (host-side, capture-safe, no allocs)
    unsigned long long *keys_in, *keys_out;
    unsigned int *vals_in, *vals_out;
    void* tempbuf;
    cudaGetSymbolAddress((void**)&keys_in,  g_keys64);
    cudaGetSymbolAddress((void**)&keys_out, g_keys64_out);
    cudaGetSymbolAddress((void**)&vals_in,  g_vals);
    cudaGetSymbolAddress((void**)&vals_out, g_vals_out);
    cudaGetSymbolAddress(&tempbuf,          g_temp);

    // Full-device onesweep radix sort over 37-bit composite keys:
    // full-chip occupancy instead of 32-block segmented sort.
    size_t temp_bytes = 0;
    cub::DeviceRadixSort::SortPairsDescending(
        nullptr, temp_bytes,
        keys_in, keys_out, vals_in, vals_out,
        BB * SS, 0, 37, (cudaStream_t)0);

    if (temp_bytes > sizeof(g_temp)) temp_bytes = sizeof(g_temp);  // guarded

    cub::DeviceRadixSort::SortPairsDescending(
        tempbuf, temp_bytes,
        keys_in, keys_out, vals_in, vals_out,
        BB * SS, 0, 37, (cudaStream_t)0);

    {
        long long n = (long long)BB * k * (DD / 4);
        int threads = 256;
        int blocks = (int)((n + threads - 1) / threads);
        gather_kernel<<<blocks, threads>>>(emb, out, k);
    }
}